// round 7
// baseline (speedup 1.0000x reference)
#include <cuda_runtime.h>
#include <cstdint>

#define Bb  8
#define Tt  2048
#define Cc  1024
#define HSd 64
#define Mrows (Bb*Tt)
#define NQT  32
#define MAXCH 4

// Projected q/k/v (tf32-rounded fp32 bits)
__device__ float g_q[Mrows*HSd];
__device__ float g_k[Mrows*HSd];
__device__ float g_v[Mrows*HSd];
// W, tf32-pre-rounded, layout [k][h]
__device__ float g_wt[3*Cc*HSd];
// Split-KV partials
__device__ float g_pO[Bb*NQT*MAXCH*64*64];
__device__ float g_pm[Bb*NQT*MAXCH*64];
__device__ float g_pl[Bb*NQT*MAXCH*64];

__device__ __forceinline__ uint32_t f2tf(float f) {
    uint32_t u;
    asm("cvt.rna.tf32.f32 %0, %1;" : "=r"(u) : "f"(f));
    return u;
}
__device__ __forceinline__ float tfv(float f) { return __uint_as_float(f2tf(f)); }
__device__ __forceinline__ float ex2(float x) {
    float r;
    asm("ex2.approx.ftz.f32 %0, %1;" : "=f"(r) : "f"(x));
    return r;
}
__device__ __forceinline__ void mma8(float* c, const uint32_t* a, uint32_t b0, uint32_t b1) {
    asm volatile(
        "mma.sync.aligned.m16n8k8.row.col.f32.tf32.tf32.f32 "
        "{%0,%1,%2,%3},{%4,%5,%6,%7},{%8,%9},{%0,%1,%2,%3};"
        : "+f"(c[0]), "+f"(c[1]), "+f"(c[2]), "+f"(c[3])
        : "r"(a[0]), "r"(a[1]), "r"(a[2]), "r"(a[3]), "r"(b0), "r"(b1));
}
__device__ __forceinline__ void cp16(uint32_t dst, const void* src) {
    asm volatile("cp.async.ca.shared.global [%0], [%1], 16;" :: "r"(dst), "l"(src));
}
#define CP_COMMIT() asm volatile("cp.async.commit_group;")
#define CP_WAIT0()  asm volatile("cp.async.wait_group 0;")

// ---------------------------------------------------------------------------
// Prep: tf32-round W, layout unchanged [k][h].
// ---------------------------------------------------------------------------
__global__ __launch_bounds__(256)
void prep_w(const float* __restrict__ Wq, const float* __restrict__ Wk,
            const float* __restrict__ Wv)
{
    const int m = blockIdx.y;
    const float* W = (m == 0) ? Wq : ((m == 1) ? Wk : Wv);
    float* outp = g_wt + (size_t)m * Cc * HSd;
    const int i = (blockIdx.x * 256 + threadIdx.x) * 4;
    float4 v = *(const float4*)(W + i);
    *(float4*)(outp + i) = make_float4(tfv(v.x), tfv(v.y), tfv(v.z), tfv(v.w));
}

// ---------------------------------------------------------------------------
// Projection. CTA: 128 thr (4 warps), 128 rows x 64 cols, K-chunks of 32.
// A: NO smem — fragments loaded global->reg (rows are warp-private; cols
//    tig/tig+4 share one 32B sector so DRAM traffic is exact), cvt in reg.
// W: smem only, double-buffered 8KB stages via cp.async (pre-rounded g_wt),
//    pitch 72 -> B-frag LDS conflict-free. One barrier per chunk.
// ---------------------------------------------------------------------------
__global__ __launch_bounds__(128, 4)
void proj_kernel(const float* __restrict__ qv, const float* __restrict__ kv,
                 const float* __restrict__ vv)
{
    __shared__ float Ws[2][32*72];

    const int m = blockIdx.y;
    const float* in  = (m == 0) ? qv : ((m == 1) ? kv : vv);
    float*       out = (m == 0) ? g_q : ((m == 1) ? g_k : g_v);
    const float* wt  = g_wt + (size_t)m * Cc * HSd;

    const int tid  = threadIdx.x;
    const int wid  = tid >> 5;
    const int lane = tid & 31;
    const int g    = lane >> 2;
    const int tig  = lane & 3;
    const int row0 = blockIdx.x * 128;
    const int m0w  = wid * 32;

    const int wR = tid >> 2;          // 0..31 (W k-row within chunk)
    const int wC = (tid & 3) * 16;    // 0..48 (W h-col base)

    // A row base pointers (warp-private rows)
    const float* a0p = in + (size_t)(row0 + m0w + g     )*Cc;
    const float* a1p = in + (size_t)(row0 + m0w + g +  8)*Cc;
    const float* a2p = in + (size_t)(row0 + m0w + g + 16)*Cc;
    const float* a3p = in + (size_t)(row0 + m0w + g + 24)*Cc;

#define LDW_ASYNC(k0, buf)                                                    \
    { const float* p = wt + (size_t)((k0) + wR)*HSd + wC;                     \
      uint32_t d = (uint32_t)__cvta_generic_to_shared(&Ws[buf][wR*72 + wC]);  \
      cp16(d, p); cp16(d + 16, p + 4);                                        \
      cp16(d + 32, p + 8); cp16(d + 48, p + 12);                              \
      CP_COMMIT(); }

    float acc[2][8][4];
#pragma unroll
    for (int mi = 0; mi < 2; mi++)
#pragma unroll
        for (int n = 0; n < 8; n++)
#pragma unroll
            for (int j = 0; j < 4; j++) acc[mi][n][j] = 0.f;

    LDW_ASYNC(0, 0);

    for (int c = 0; c < 32; c++) {
        const int cur = c & 1;
        const int kbase = 32 * c;

        // ---- batch-load all A scalars for this chunk (32 LDG in flight) ----
        float ar[4][8];
#pragma unroll
        for (int ks = 0; ks < 4; ks++) {
            const int col = kbase + 8*ks + tig;
            ar[ks][0] = a0p[col];     ar[ks][1] = a1p[col];
            ar[ks][2] = a0p[col + 4]; ar[ks][3] = a1p[col + 4];
            ar[ks][4] = a2p[col];     ar[ks][5] = a3p[col];
            ar[ks][6] = a2p[col + 4]; ar[ks][7] = a3p[col + 4];
        }

        CP_WAIT0();          // W stage c arrived (this thread's copies)
        __syncthreads();     // visible to all; prev buf's readers done
        if (c < 31) LDW_ASYNC(32*(c+1), cur ^ 1);

#pragma unroll
        for (int ks = 0; ks < 4; ks++) {
            uint32_t af0[4] = { f2tf(ar[ks][0]), f2tf(ar[ks][1]),
                                f2tf(ar[ks][2]), f2tf(ar[ks][3]) };
            uint32_t af1[4] = { f2tf(ar[ks][4]), f2tf(ar[ks][5]),
                                f2tf(ar[ks][6]), f2tf(ar[ks][7]) };
#pragma unroll
            for (int n = 0; n < 8; n++) {
                uint32_t b0 = __float_as_uint(Ws[cur][(8*ks + tig    )*72 + 8*n + g]);
                uint32_t b1 = __float_as_uint(Ws[cur][(8*ks + tig + 4)*72 + 8*n + g]);
                mma8(acc[0][n], af0, b0, b1);
                mma8(acc[1][n], af1, b0, b1);
            }
        }
    }

#pragma unroll
    for (int mi = 0; mi < 2; mi++) {
        const int rb = row0 + m0w + mi*16;
#pragma unroll
        for (int n = 0; n < 8; n++) {
            *(float2*)(out + (size_t)(rb + g    )*HSd + 8*n + 2*tig) =
                make_float2(tfv(acc[mi][n][0]), tfv(acc[mi][n][1]));
            *(float2*)(out + (size_t)(rb + g + 8)*HSd + 8*n + 2*tig) =
                make_float2(tfv(acc[mi][n][2]), tfv(acc[mi][n][3]));
        }
    }
#undef LDW_ASYNC
}

// ---------------------------------------------------------------------------
// Split-KV flash attention — EXACT round-4/6 version (known good).
// ---------------------------------------------------------------------------
__global__ __launch_bounds__(128, 4)
void attn_kernel(const int* __restrict__ mask, float* __restrict__ out)
{
    __shared__ float KP[64*68];
    __shared__ float Vs[64*72];
    __shared__ int   msk[64];

    const int i = blockIdx.x;
    const int b = i & 7;
    const int r = i >> 3;
    int qb, chunk;
    if (r < 32)      { qb = 24 + (r >> 2);       chunk = r & 3; }
    else if (r < 56) { int t = r - 32; qb = 16 + t/3; chunk = t - 3*(t/3); }
    else if (r < 72) { int t = r - 56; qb = 8 + (t >> 1); chunk = t & 1; }
    else             { qb = r - 72;              chunk = 0; }
    const int nch   = (qb + 8) >> 3;
    const int kb_lo = chunk * 8;
    const int kb_hi = min(kb_lo + 8, qb + 1);

    const int q0   = qb * 64;
    const int tid  = threadIdx.x;
    const int wid  = tid >> 5;
    const int lane = tid & 31;
    const int g    = lane >> 2;
    const int tig  = lane & 3;
    const int m0w  = wid * 16;

    uint32_t qf[8][4];
    const float* qbase = g_q + (size_t)(b*Tt + q0 + m0w)*HSd;
#pragma unroll
    for (int k = 0; k < 8; k++) {
        qf[k][0] = __float_as_uint(qbase[(g    )*HSd + 8*k + tig    ]);
        qf[k][1] = __float_as_uint(qbase[(g + 8)*HSd + 8*k + tig    ]);
        qf[k][2] = __float_as_uint(qbase[(g    )*HSd + 8*k + tig + 4]);
        qf[k][3] = __float_as_uint(qbase[(g + 8)*HSd + 8*k + tig + 4]);
    }

    float o[8][4];
#pragma unroll
    for (int n = 0; n < 8; n++)
#pragma unroll
        for (int j = 0; j < 4; j++) o[n][j] = 0.f;
    float mr0 = -1e30f, mr1 = -1e30f, lr0 = 0.f, lr1 = 0.f;

    const float scale2 = 0.125f * 1.4426950408889634f;
    const int row0g = q0 + m0w + g;
    const int row1g = row0g + 8;

    for (int kb = kb_lo; kb < kb_hi; kb++) {
        const int k0 = kb * 64;
        __syncthreads();

        const float* kg = g_k + (size_t)(b*Tt + k0)*HSd;
        const float* vg = g_v + (size_t)(b*Tt + k0)*HSd;
#pragma unroll
        for (int t = tid; t < 1024; t += 128) {
            int rr = t >> 4, c4 = (t & 15) << 2;
            *(float4*)&KP[rr*68 + c4] = *(const float4*)(kg + rr*HSd + c4);
            *(float4*)&Vs[rr*72 + c4] = *(const float4*)(vg + rr*HSd + c4);
        }
        if (tid < 64) msk[tid] = mask[b*Tt + k0 + tid];
        __syncthreads();

        float s[8][4];
#pragma unroll
        for (int n = 0; n < 8; n++)
#pragma unroll
            for (int j = 0; j < 4; j++) s[n][j] = 0.f;
#pragma unroll
        for (int k = 0; k < 8; k++) {
#pragma unroll
            for (int n = 0; n < 8; n++) {
                uint32_t b0 = __float_as_uint(KP[(8*n + g)*68 + 8*k + tig    ]);
                uint32_t b1 = __float_as_uint(KP[(8*n + g)*68 + 8*k + tig + 4]);
                mma8(s[n], qf[k], b0, b1);
            }
        }

        const bool diag = (kb == qb);
#pragma unroll
        for (int n = 0; n < 8; n++) {
            int cl = 8*n + 2*tig;
            int2 mm = *(const int2*)&msk[cl];
            int c0 = k0 + cl, c1 = c0 + 1;
            bool v00 = (mm.x != 0) && (!diag || c0 <= row0g);
            bool v01 = (mm.y != 0) && (!diag || c1 <= row0g);
            bool v10 = (mm.x != 0) && (!diag || c0 <= row1g);
            bool v11 = (mm.y != 0) && (!diag || c1 <= row1g);
            s[n][0] = v00 ? s[n][0]*scale2 : -1e30f;
            s[n][1] = v01 ? s[n][1]*scale2 : -1e30f;
            s[n][2] = v10 ? s[n][2]*scale2 : -1e30f;
            s[n][3] = v11 ? s[n][3]*scale2 : -1e30f;
        }

        {
            float m0 = -1e30f, m1 = -1e30f;
#pragma unroll
            for (int n = 0; n < 8; n++) {
                m0 = fmaxf(m0, fmaxf(s[n][0], s[n][1]));
                m1 = fmaxf(m1, fmaxf(s[n][2], s[n][3]));
            }
#pragma unroll
            for (int off = 1; off < 4; off <<= 1) {
                m0 = fmaxf(m0, __shfl_xor_sync(0xffffffffu, m0, off));
                m1 = fmaxf(m1, __shfl_xor_sync(0xffffffffu, m1, off));
            }
            float mn0 = fmaxf(mr0, m0), mn1 = fmaxf(mr1, m1);
            float al0 = ex2(mr0 - mn0), al1 = ex2(mr1 - mn1);
            float ls0 = 0.f, ls1 = 0.f;
#pragma unroll
            for (int n = 0; n < 8; n++) {
                s[n][0] = ex2(s[n][0] - mn0);
                s[n][1] = ex2(s[n][1] - mn0);
                s[n][2] = ex2(s[n][2] - mn1);
                s[n][3] = ex2(s[n][3] - mn1);
                ls0 += s[n][0] + s[n][1];
                ls1 += s[n][2] + s[n][3];
            }
#pragma unroll
            for (int off = 1; off < 4; off <<= 1) {
                ls0 += __shfl_xor_sync(0xffffffffu, ls0, off);
                ls1 += __shfl_xor_sync(0xffffffffu, ls1, off);
            }
            lr0 = lr0*al0 + ls0;  mr0 = mn0;
            lr1 = lr1*al1 + ls1;  mr1 = mn1;
#pragma unroll
            for (int n = 0; n < 8; n++) {
                o[n][0] *= al0; o[n][1] *= al0;
                o[n][2] *= al1; o[n][3] *= al1;
            }
        }

        __syncthreads();
#pragma unroll
        for (int n = 0; n < 8; n++) {
            float2 p0 = make_float2(tfv(s[n][0]), tfv(s[n][1]));
            float2 p1 = make_float2(tfv(s[n][2]), tfv(s[n][3]));
            *(float2*)&KP[(m0w + g    )*68 + 8*n + 2*tig] = p0;
            *(float2*)&KP[(m0w + g + 8)*68 + 8*n + 2*tig] = p1;
        }
        __syncwarp();

#pragma unroll
        for (int k = 0; k < 8; k++) {
            uint32_t af[4];
            af[0] = __float_as_uint(KP[(m0w + g    )*68 + 8*k + tig    ]);
            af[1] = __float_as_uint(KP[(m0w + g + 8)*68 + 8*k + tig    ]);
            af[2] = __float_as_uint(KP[(m0w + g    )*68 + 8*k + tig + 4]);
            af[3] = __float_as_uint(KP[(m0w + g + 8)*68 + 8*k + tig + 4]);
#pragma unroll
            for (int n = 0; n < 8; n++) {
                uint32_t b0 = __float_as_uint(Vs[(8*k + tig    )*72 + 8*n + g]);
                uint32_t b1 = __float_as_uint(Vs[(8*k + tig + 4)*72 + 8*n + g]);
                mma8(o[n], af, b0, b1);
            }
        }
    }

    if (nch == 1) {
        const float inv0 = 1.0f / lr0, inv1 = 1.0f / lr1;
        float* obase = out + (size_t)(b*Tt + q0 + m0w)*HSd;
#pragma unroll
        for (int n = 0; n < 8; n++) {
            *(float2*)(obase + (g    )*HSd + 8*n + 2*tig) =
                make_float2(o[n][0]*inv0, o[n][1]*inv0);
            *(float2*)(obase + (g + 8)*HSd + 8*n + 2*tig) =
                make_float2(o[n][2]*inv1, o[n][3]*inv1);
        }
    } else {
        const size_t idx = (size_t)((b*NQT + qb)*MAXCH + chunk);
        float* pO = g_pO + idx*4096;
#pragma unroll
        for (int n = 0; n < 8; n++) {
            *(float2*)&pO[(m0w + g    )*64 + 8*n + 2*tig] =
                make_float2(o[n][0], o[n][1]);
            *(float2*)&pO[(m0w + g + 8)*64 + 8*n + 2*tig] =
                make_float2(o[n][2], o[n][3]);
        }
        if (tig == 0) {
            g_pm[idx*64 + m0w + g    ] = mr0;
            g_pl[idx*64 + m0w + g    ] = lr0;
            g_pm[idx*64 + m0w + g + 8] = mr1;
            g_pl[idx*64 + m0w + g + 8] = lr1;
        }
    }
}

// ---------------------------------------------------------------------------
// Combine partials for qb >= 8. Grid (24, 8) x 512 thr.
// ---------------------------------------------------------------------------
__global__ __launch_bounds__(512)
void combine_kernel(float* __restrict__ out)
{
    const int qb  = 8 + blockIdx.x;
    const int b   = blockIdx.y;
    const int nch = (qb + 8) >> 3;
    const int t   = threadIdx.x;
    const int row = t >> 3;
    const int oc  = (t & 7) * 8;
    const int base = (b*NQT + qb)*MAXCH;

    float mg = -1e30f;
    for (int i = 0; i < nch; i++)
        mg = fmaxf(mg, g_pm[(base + i)*64 + row]);

    float l = 0.f;
    float4 acc[2];
    acc[0] = make_float4(0.f, 0.f, 0.f, 0.f);
    acc[1] = make_float4(0.f, 0.f, 0.f, 0.f);

    for (int i = 0; i < nch; i++) {
        float w = ex2(g_pm[(base + i)*64 + row] - mg);
        l += w * g_pl[(base + i)*64 + row];
        const float4* src = (const float4*)&g_pO[(size_t)(base + i)*4096 + row*64 + oc];
#pragma unroll
        for (int j = 0; j < 2; j++) {
            float4 v = src[j];
            acc[j].x += w*v.x; acc[j].y += w*v.y;
            acc[j].z += w*v.z; acc[j].w += w*v.w;
        }
    }

    const float inv = 1.0f / l;
    float4* dst = (float4*)(out + (size_t)(b*Tt + qb*64 + row)*HSd + oc);
#pragma unroll
    for (int j = 0; j < 2; j++)
        dst[j] = make_float4(acc[j].x*inv, acc[j].y*inv, acc[j].z*inv, acc[j].w*inv);
}

// ---------------------------------------------------------------------------
extern "C" void kernel_launch(void* const* d_in, const int* in_sizes, int n_in,
                              void* d_out, int out_size)
{
    const float* q_vec = (const float*)d_in[0];
    const float* k_vec = (const float*)d_in[1];
    const float* v_vec = (const float*)d_in[2];
    const int*   mask  = (const int*)  d_in[3];
    const float* Wq    = (const float*)d_in[4];
    const float* Wk    = (const float*)d_in[5];
    const float* Wv    = (const float*)d_in[6];
    float* out = (float*)d_out;

    prep_w<<<dim3(Cc*HSd/1024, 3), 256>>>(Wq, Wk, Wv);
    proj_kernel<<<dim3(Mrows/128, 3), 128>>>(q_vec, k_vec, v_vec);
    attn_kernel<<<640, 128>>>(mask, out);
    combine_kernel<<<dim3(24, 8), 512>>>(out);
}

// round 8
// speedup vs baseline: 1.0196x; 1.0196x over previous
#include <cuda_runtime.h>
#include <cstdint>

#define Bb  8
#define Tt  2048
#define Cc  1024
#define HSd 64
#define Mrows (Bb*Tt)
#define NQT  32
#define MAXCH 4
#define APCH 24            // proj A pitch for 16-col chunks (conflict-free pairs)

// Projected q/k/v (tf32-rounded fp32 bits)
__device__ float g_q[Mrows*HSd];
__device__ float g_k[Mrows*HSd];
__device__ float g_v[Mrows*HSd];
// W, tf32-pre-rounded, layout [k][h]
__device__ float g_wt[3*Cc*HSd];
// Split-KV partials
__device__ float g_pO[Bb*NQT*MAXCH*64*64];
__device__ float g_pm[Bb*NQT*MAXCH*64];
__device__ float g_pl[Bb*NQT*MAXCH*64];

__device__ __forceinline__ uint32_t f2tf(float f) {
    uint32_t u;
    asm("cvt.rna.tf32.f32 %0, %1;" : "=r"(u) : "f"(f));
    return u;
}
__device__ __forceinline__ float tfv(float f) { return __uint_as_float(f2tf(f)); }
__device__ __forceinline__ float ex2(float x) {
    float r;
    asm("ex2.approx.ftz.f32 %0, %1;" : "=f"(r) : "f"(x));
    return r;
}
__device__ __forceinline__ void mma8(float* c, const uint32_t* a, uint32_t b0, uint32_t b1) {
    asm volatile(
        "mma.sync.aligned.m16n8k8.row.col.f32.tf32.tf32.f32 "
        "{%0,%1,%2,%3},{%4,%5,%6,%7},{%8,%9},{%0,%1,%2,%3};"
        : "+f"(c[0]), "+f"(c[1]), "+f"(c[2]), "+f"(c[3])
        : "r"(a[0]), "r"(a[1]), "r"(a[2]), "r"(a[3]), "r"(b0), "r"(b1));
}

// ---------------------------------------------------------------------------
// Prep: tf32-round W, layout unchanged [k][h].
// ---------------------------------------------------------------------------
__global__ __launch_bounds__(256)
void prep_w(const float* __restrict__ Wq, const float* __restrict__ Wk,
            const float* __restrict__ Wv)
{
    const int m = blockIdx.y;
    const float* W = (m == 0) ? Wq : ((m == 1) ? Wk : Wv);
    float* outp = g_wt + (size_t)m * Cc * HSd;
    const int i = (blockIdx.x * 256 + threadIdx.x) * 4;
    float4 v = *(const float4*)(W + i);
    *(float4*)(outp + i) = make_float4(tfv(v.x), tfv(v.y), tfv(v.z), tfv(v.w));
}

// ---------------------------------------------------------------------------
// Projection — r6 pipeline skeleton, K-chunks of 16 (occupancy-focused).
// CTA: 128 thr (4 warps), 128 rows x 64 cols. Each warp: 2 m16 tiles,
// B fragments amortized over 2 mmas. A smem pitch 24, k-permuted pairs ->
// LDS.64 fragment loads conflict-free. W smem pitch 72 (pre-rounded g_wt).
// Double-buffered LDG->reg->STS, one barrier per chunk, 64 chunks.
// Smem 33.8 KB static; launch_bounds(128,4) -> 16 warps/SM.
// ---------------------------------------------------------------------------
__global__ __launch_bounds__(128, 4)
void proj_kernel(const float* __restrict__ qv, const float* __restrict__ kv,
                 const float* __restrict__ vv)
{
    __shared__ float As[2][128*APCH];
    __shared__ float Ws[2][16*72];

    const int m = blockIdx.y;
    const float* in  = (m == 0) ? qv : ((m == 1) ? kv : vv);
    float*       out = (m == 0) ? g_q : ((m == 1) ? g_k : g_v);
    const float* wt  = g_wt + (size_t)m * Cc * HSd;

    const int tid  = threadIdx.x;
    const int wid  = tid >> 5;
    const int lane = tid & 31;
    const int g    = lane >> 2;
    const int tig  = lane & 3;
    const int row0 = blockIdx.x * 128;
    const int m0w  = wid * 32;

    const int aR = tid >> 1;          // 0..63 (+64*i)
    const int aC = (tid & 1) * 8;     // 0 or 8
    const int wR = tid >> 3;          // 0..15
    const int wC = (tid & 7) * 8;     // 0..56

    float4 pa[4];                     // A stage: 2 rows x 8 floats
    float4 pw[2];                     // W stage: 8 floats

#define LDA(k0)                                                               \
    { _Pragma("unroll") for (int i = 0; i < 2; i++) {                         \
        const float* p = in + (size_t)(row0 + aR + 64*i)*Cc + (k0) + aC;      \
        pa[2*i]   = *(const float4*)p;                                        \
        pa[2*i+1] = *(const float4*)(p + 4); } }

#define LDWm(k0)                                                              \
    { const float* p = wt + (size_t)((k0) + wR)*HSd + wC;                     \
      pw[0] = *(const float4*)p;                                              \
      pw[1] = *(const float4*)(p + 4); }

#define STAB(buf)                                                             \
    { _Pragma("unroll") for (int i = 0; i < 2; i++) {                         \
        float4 a = pa[2*i], b = pa[2*i+1];                                    \
        *(float4*)&(buf)[(aR + 64*i)*APCH + aC] =                             \
            make_float4(tfv(a.x), tfv(b.x), tfv(a.y), tfv(b.y));              \
        *(float4*)&(buf)[(aR + 64*i)*APCH + aC + 4] =                         \
            make_float4(tfv(a.z), tfv(b.z), tfv(a.w), tfv(b.w)); } }

#define STWB(buf)                                                             \
    { *(float4*)&(buf)[wR*72 + wC]     = pw[0];                               \
      *(float4*)&(buf)[wR*72 + wC + 4] = pw[1]; }

    float acc[2][8][4];
#pragma unroll
    for (int mi = 0; mi < 2; mi++)
#pragma unroll
        for (int n = 0; n < 8; n++)
#pragma unroll
            for (int j = 0; j < 4; j++) acc[mi][n][j] = 0.f;

    LDA(0); LDWm(0);
    STAB(As[0]); STWB(Ws[0]);
    __syncthreads();

    for (int c = 0; c < 64; c++) {
        const int cur = c & 1;

        if (c < 63) { LDA(16*(c+1)); LDWm(16*(c+1)); }

#pragma unroll
        for (int ks = 0; ks < 2; ks++) {
            float2 a0 = *(const float2*)&As[cur][(m0w + g     )*APCH + 8*ks + 2*tig];
            float2 a1 = *(const float2*)&As[cur][(m0w + g +  8)*APCH + 8*ks + 2*tig];
            float2 a2 = *(const float2*)&As[cur][(m0w + g + 16)*APCH + 8*ks + 2*tig];
            float2 a3 = *(const float2*)&As[cur][(m0w + g + 24)*APCH + 8*ks + 2*tig];
            uint32_t af0[4] = { __float_as_uint(a0.x), __float_as_uint(a1.x),
                                __float_as_uint(a0.y), __float_as_uint(a1.y) };
            uint32_t af1[4] = { __float_as_uint(a2.x), __float_as_uint(a3.x),
                                __float_as_uint(a2.y), __float_as_uint(a3.y) };
#pragma unroll
            for (int n = 0; n < 8; n++) {
                uint32_t b0 = __float_as_uint(Ws[cur][(8*ks + tig    )*72 + 8*n + g]);
                uint32_t b1 = __float_as_uint(Ws[cur][(8*ks + tig + 4)*72 + 8*n + g]);
                mma8(acc[0][n], af0, b0, b1);
                mma8(acc[1][n], af1, b0, b1);
            }
        }
        if (c < 63) { STAB(As[cur ^ 1]); STWB(Ws[cur ^ 1]); }
        __syncthreads();
    }

#pragma unroll
    for (int mi = 0; mi < 2; mi++) {
        const int rb = row0 + m0w + mi*16;
#pragma unroll
        for (int n = 0; n < 8; n++) {
            *(float2*)(out + (size_t)(rb + g    )*HSd + 8*n + 2*tig) =
                make_float2(tfv(acc[mi][n][0]), tfv(acc[mi][n][1]));
            *(float2*)(out + (size_t)(rb + g + 8)*HSd + 8*n + 2*tig) =
                make_float2(tfv(acc[mi][n][2]), tfv(acc[mi][n][3]));
        }
    }
#undef LDA
#undef LDWm
#undef STAB
#undef STWB
}

// ---------------------------------------------------------------------------
// Split-KV flash attention — EXACT round-4/6 version (known good).
// ---------------------------------------------------------------------------
__global__ __launch_bounds__(128, 4)
void attn_kernel(const int* __restrict__ mask, float* __restrict__ out)
{
    __shared__ float KP[64*68];
    __shared__ float Vs[64*72];
    __shared__ int   msk[64];

    const int i = blockIdx.x;
    const int b = i & 7;
    const int r = i >> 3;
    int qb, chunk;
    if (r < 32)      { qb = 24 + (r >> 2);       chunk = r & 3; }
    else if (r < 56) { int t = r - 32; qb = 16 + t/3; chunk = t - 3*(t/3); }
    else if (r < 72) { int t = r - 56; qb = 8 + (t >> 1); chunk = t & 1; }
    else             { qb = r - 72;              chunk = 0; }
    const int nch   = (qb + 8) >> 3;
    const int kb_lo = chunk * 8;
    const int kb_hi = min(kb_lo + 8, qb + 1);

    const int q0   = qb * 64;
    const int tid  = threadIdx.x;
    const int wid  = tid >> 5;
    const int lane = tid & 31;
    const int g    = lane >> 2;
    const int tig  = lane & 3;
    const int m0w  = wid * 16;

    uint32_t qf[8][4];
    const float* qbase = g_q + (size_t)(b*Tt + q0 + m0w)*HSd;
#pragma unroll
    for (int k = 0; k < 8; k++) {
        qf[k][0] = __float_as_uint(qbase[(g    )*HSd + 8*k + tig    ]);
        qf[k][1] = __float_as_uint(qbase[(g + 8)*HSd + 8*k + tig    ]);
        qf[k][2] = __float_as_uint(qbase[(g    )*HSd + 8*k + tig + 4]);
        qf[k][3] = __float_as_uint(qbase[(g + 8)*HSd + 8*k + tig + 4]);
    }

    float o[8][4];
#pragma unroll
    for (int n = 0; n < 8; n++)
#pragma unroll
        for (int j = 0; j < 4; j++) o[n][j] = 0.f;
    float mr0 = -1e30f, mr1 = -1e30f, lr0 = 0.f, lr1 = 0.f;

    const float scale2 = 0.125f * 1.4426950408889634f;
    const int row0g = q0 + m0w + g;
    const int row1g = row0g + 8;

    for (int kb = kb_lo; kb < kb_hi; kb++) {
        const int k0 = kb * 64;
        __syncthreads();

        const float* kg = g_k + (size_t)(b*Tt + k0)*HSd;
        const float* vg = g_v + (size_t)(b*Tt + k0)*HSd;
#pragma unroll
        for (int t = tid; t < 1024; t += 128) {
            int rr = t >> 4, c4 = (t & 15) << 2;
            *(float4*)&KP[rr*68 + c4] = *(const float4*)(kg + rr*HSd + c4);
            *(float4*)&Vs[rr*72 + c4] = *(const float4*)(vg + rr*HSd + c4);
        }
        if (tid < 64) msk[tid] = mask[b*Tt + k0 + tid];
        __syncthreads();

        float s[8][4];
#pragma unroll
        for (int n = 0; n < 8; n++)
#pragma unroll
            for (int j = 0; j < 4; j++) s[n][j] = 0.f;
#pragma unroll
        for (int k = 0; k < 8; k++) {
#pragma unroll
            for (int n = 0; n < 8; n++) {
                uint32_t b0 = __float_as_uint(KP[(8*n + g)*68 + 8*k + tig    ]);
                uint32_t b1 = __float_as_uint(KP[(8*n + g)*68 + 8*k + tig + 4]);
                mma8(s[n], qf[k], b0, b1);
            }
        }

        const bool diag = (kb == qb);
#pragma unroll
        for (int n = 0; n < 8; n++) {
            int cl = 8*n + 2*tig;
            int2 mm = *(const int2*)&msk[cl];
            int c0 = k0 + cl, c1 = c0 + 1;
            bool v00 = (mm.x != 0) && (!diag || c0 <= row0g);
            bool v01 = (mm.y != 0) && (!diag || c1 <= row0g);
            bool v10 = (mm.x != 0) && (!diag || c0 <= row1g);
            bool v11 = (mm.y != 0) && (!diag || c1 <= row1g);
            s[n][0] = v00 ? s[n][0]*scale2 : -1e30f;
            s[n][1] = v01 ? s[n][1]*scale2 : -1e30f;
            s[n][2] = v10 ? s[n][2]*scale2 : -1e30f;
            s[n][3] = v11 ? s[n][3]*scale2 : -1e30f;
        }

        {
            float m0 = -1e30f, m1 = -1e30f;
#pragma unroll
            for (int n = 0; n < 8; n++) {
                m0 = fmaxf(m0, fmaxf(s[n][0], s[n][1]));
                m1 = fmaxf(m1, fmaxf(s[n][2], s[n][3]));
            }
#pragma unroll
            for (int off = 1; off < 4; off <<= 1) {
                m0 = fmaxf(m0, __shfl_xor_sync(0xffffffffu, m0, off));
                m1 = fmaxf(m1, __shfl_xor_sync(0xffffffffu, m1, off));
            }
            float mn0 = fmaxf(mr0, m0), mn1 = fmaxf(mr1, m1);
            float al0 = ex2(mr0 - mn0), al1 = ex2(mr1 - mn1);
            float ls0 = 0.f, ls1 = 0.f;
#pragma unroll
            for (int n = 0; n < 8; n++) {
                s[n][0] = ex2(s[n][0] - mn0);
                s[n][1] = ex2(s[n][1] - mn0);
                s[n][2] = ex2(s[n][2] - mn1);
                s[n][3] = ex2(s[n][3] - mn1);
                ls0 += s[n][0] + s[n][1];
                ls1 += s[n][2] + s[n][3];
            }
#pragma unroll
            for (int off = 1; off < 4; off <<= 1) {
                ls0 += __shfl_xor_sync(0xffffffffu, ls0, off);
                ls1 += __shfl_xor_sync(0xffffffffu, ls1, off);
            }
            lr0 = lr0*al0 + ls0;  mr0 = mn0;
            lr1 = lr1*al1 + ls1;  mr1 = mn1;
#pragma unroll
            for (int n = 0; n < 8; n++) {
                o[n][0] *= al0; o[n][1] *= al0;
                o[n][2] *= al1; o[n][3] *= al1;
            }
        }

        __syncthreads();
#pragma unroll
        for (int n = 0; n < 8; n++) {
            float2 p0 = make_float2(tfv(s[n][0]), tfv(s[n][1]));
            float2 p1 = make_float2(tfv(s[n][2]), tfv(s[n][3]));
            *(float2*)&KP[(m0w + g    )*68 + 8*n + 2*tig] = p0;
            *(float2*)&KP[(m0w + g + 8)*68 + 8*n + 2*tig] = p1;
        }
        __syncwarp();

#pragma unroll
        for (int k = 0; k < 8; k++) {
            uint32_t af[4];
            af[0] = __float_as_uint(KP[(m0w + g    )*68 + 8*k + tig    ]);
            af[1] = __float_as_uint(KP[(m0w + g + 8)*68 + 8*k + tig    ]);
            af[2] = __float_as_uint(KP[(m0w + g    )*68 + 8*k + tig + 4]);
            af[3] = __float_as_uint(KP[(m0w + g + 8)*68 + 8*k + tig + 4]);
#pragma unroll
            for (int n = 0; n < 8; n++) {
                uint32_t b0 = __float_as_uint(Vs[(8*k + tig    )*72 + 8*n + g]);
                uint32_t b1 = __float_as_uint(Vs[(8*k + tig + 4)*72 + 8*n + g]);
                mma8(o[n], af, b0, b1);
            }
        }
    }

    if (nch == 1) {
        const float inv0 = 1.0f / lr0, inv1 = 1.0f / lr1;
        float* obase = out + (size_t)(b*Tt + q0 + m0w)*HSd;
#pragma unroll
        for (int n = 0; n < 8; n++) {
            *(float2*)(obase + (g    )*HSd + 8*n + 2*tig) =
                make_float2(o[n][0]*inv0, o[n][1]*inv0);
            *(float2*)(obase + (g + 8)*HSd + 8*n + 2*tig) =
                make_float2(o[n][2]*inv1, o[n][3]*inv1);
        }
    } else {
        const size_t idx = (size_t)((b*NQT + qb)*MAXCH + chunk);
        float* pO = g_pO + idx*4096;
#pragma unroll
        for (int n = 0; n < 8; n++) {
            *(float2*)&pO[(m0w + g    )*64 + 8*n + 2*tig] =
                make_float2(o[n][0], o[n][1]);
            *(float2*)&pO[(m0w + g + 8)*64 + 8*n + 2*tig] =
                make_float2(o[n][2], o[n][3]);
        }
        if (tig == 0) {
            g_pm[idx*64 + m0w + g    ] = mr0;
            g_pl[idx*64 + m0w + g    ] = lr0;
            g_pm[idx*64 + m0w + g + 8] = mr1;
            g_pl[idx*64 + m0w + g + 8] = lr1;
        }
    }
}

// ---------------------------------------------------------------------------
// Combine partials for qb >= 8. Grid (24, 8) x 512 thr.
// ---------------------------------------------------------------------------
__global__ __launch_bounds__(512)
void combine_kernel(float* __restrict__ out)
{
    const int qb  = 8 + blockIdx.x;
    const int b   = blockIdx.y;
    const int nch = (qb + 8) >> 3;
    const int t   = threadIdx.x;
    const int row = t >> 3;
    const int oc  = (t & 7) * 8;
    const int base = (b*NQT + qb)*MAXCH;

    float mg = -1e30f;
    for (int i = 0; i < nch; i++)
        mg = fmaxf(mg, g_pm[(base + i)*64 + row]);

    float l = 0.f;
    float4 acc[2];
    acc[0] = make_float4(0.f, 0.f, 0.f, 0.f);
    acc[1] = make_float4(0.f, 0.f, 0.f, 0.f);

    for (int i = 0; i < nch; i++) {
        float w = ex2(g_pm[(base + i)*64 + row] - mg);
        l += w * g_pl[(base + i)*64 + row];
        const float4* src = (const float4*)&g_pO[(size_t)(base + i)*4096 + row*64 + oc];
#pragma unroll
        for (int j = 0; j < 2; j++) {
            float4 v = src[j];
            acc[j].x += w*v.x; acc[j].y += w*v.y;
            acc[j].z += w*v.z; acc[j].w += w*v.w;
        }
    }

    const float inv = 1.0f / l;
    float4* dst = (float4*)(out + (size_t)(b*Tt + qb*64 + row)*HSd + oc);
#pragma unroll
    for (int j = 0; j < 2; j++)
        dst[j] = make_float4(acc[j].x*inv, acc[j].y*inv, acc[j].z*inv, acc[j].w*inv);
}

// ---------------------------------------------------------------------------
extern "C" void kernel_launch(void* const* d_in, const int* in_sizes, int n_in,
                              void* d_out, int out_size)
{
    const float* q_vec = (const float*)d_in[0];
    const float* k_vec = (const float*)d_in[1];
    const float* v_vec = (const float*)d_in[2];
    const int*   mask  = (const int*)  d_in[3];
    const float* Wq    = (const float*)d_in[4];
    const float* Wk    = (const float*)d_in[5];
    const float* Wv    = (const float*)d_in[6];
    float* out = (float*)d_out;

    prep_w<<<dim3(Cc*HSd/1024, 3), 256>>>(Wq, Wk, Wv);
    proj_kernel<<<dim3(Mrows/128, 3), 128>>>(q_vec, k_vec, v_vec);
    attn_kernel<<<640, 128>>>(mask, out);
    combine_kernel<<<dim3(24, 8), 512>>>(out);
}